// round 13
// baseline (speedup 1.0000x reference)
#include <cuda_runtime.h>
#include <cstdint>

// Spikformer SSA on GB300 — fp32 GEMMs via packed fma.rn.f32x2 (FFMA2, rt=2,
// ~73 TF/s fp32 ceiling). Numerics: sequential ascending-k fp32 FMA chain per
// output == cuBLAS sgemm == reference (rel_err 0.0). DO NOT reorder accumulation.
// R13: __launch_bounds__(256,1) -> 255-reg budget, 1 CTA/SM, 2 warps/SMSP.
// ILP-based latency hiding: ptxas can prefetch operands 2-3 kk ahead.

#define NC 512
#define NL 1024

typedef unsigned long long u64;
typedef unsigned int u32;

// ---------------- device globals ----------------
__device__ float g_Y[24][NC][NL];
__device__ float g_Z[32][NC][NL];
__device__ float g_X[32][NC][NL];
__device__ float g_bmean[3][NC];
__device__ float g_binv[3][NC];
__device__ u64   g_KVn[2][4][8][8][64][16];
__device__ u64   g_Qd[4][8][8][NL];
__device__ float g_ktv[4][8][8][64][64];
__device__ float g_fmean[NC];
__device__ float g_finv[NC];
__device__ int   g_sink;

// ---------------- helpers ----------------
__device__ __forceinline__ unsigned lif4_const(float x, float vth) {
    float v = 0.f;
    unsigned bits = 0;
#pragma unroll
    for (int t = 0; t < 4; t++) {
        v = __fadd_rn(v, __fmul_rn(__fsub_rn(x, v), 0.5f));
        if (v >= vth) { bits |= 1u << t; v = 0.f; }
    }
    return bits;
}

__device__ __forceinline__ void fma2(u64& c, u64 a, u64 b) {
    asm("fma.rn.f32x2 %0, %1, %2, %3;" : "=l"(c) : "l"(a), "l"(b), "l"(c));
}

__device__ __forceinline__ u32 smem_u32(const void* p) {
    u32 a;
    asm("{ .reg .u64 t; cvta.to.shared.u64 t, %1; cvt.u32.u64 %0, t; }" : "=r"(a) : "l"(p));
    return a;
}

#define CP_ASYNC16(dst, src) \
    asm volatile("cp.async.ca.shared.global [%0], [%1], 16;" :: "r"(dst), "l"(src))
#define CP_COMMIT() asm volatile("cp.async.commit_group;" ::: "memory")
#define CP_WAIT0()  asm volatile("cp.async.wait_group 0;" ::: "memory")

// dummy kernels so ncu's fixed "-s 5 -c 1" capture lands on k_gemm1
__global__ void k_nop1() { if (threadIdx.x == 1u << 31) g_sink = 1; }
__global__ void k_nop2() { if (threadIdx.x == 1u << 31) g_sink = 2; }
__global__ void k_nop3() { if (threadIdx.x == 1u << 31) g_sink = 3; }

// ---------------- packed-fp32 SGEMM: C_tile[128,128], K=512, chunk=16, dbuf ------
// Thread (tx,ty): rows ty*8..+8, col pairs jp*32+tx*2.
__device__ __forceinline__ void sgemm_x2(const float* __restrict__ A,
                                         const float* __restrict__ B,
                                         float* __restrict__ C,
                                         const float* __restrict__ bias) {
    __shared__ float As2[2][16][256];   // A duplicated (v,v): 16KB per buffer
    __shared__ float Bs[2][16][128];    // B verbatim: 8KB per buffer
    const int tid = threadIdx.x;
    const int tx = tid & 15, ty = tid >> 4;
    const int rowBase = blockIdx.y * 128, colBase = blockIdx.x * 128;

    const int aRow = tid >> 1, aK = (tid & 1) * 8;
    const float* ApBase = A + (size_t)(rowBase + aRow) * 512 + aK;
    const int bRow = tid >> 4, bSeg = tid & 15;
    const float* BpBase = B + (size_t)bRow * NL + colBase + bSeg * 8;
    u32 bDst0 = smem_u32(&Bs[0][bRow][bSeg * 8]);
    u32 bDst1 = smem_u32(&Bs[1][bRow][bSeg * 8]);

    u64 acc[8][4];
#pragma unroll
    for (int i = 0; i < 8; i++)
#pragma unroll
        for (int j = 0; j < 4; j++) acc[i][j] = 0ull;

    float4 a4lo, a4hi;

    // prologue: chunk 0
    CP_ASYNC16(bDst0, BpBase);
    CP_ASYNC16(bDst0 + 16, BpBase + 4);
    CP_COMMIT();
    a4lo = *(const float4*)ApBase;
    a4hi = *(const float4*)(ApBase + 4);
    {
        float av[8] = {a4lo.x, a4lo.y, a4lo.z, a4lo.w, a4hi.x, a4hi.y, a4hi.z, a4hi.w};
#pragma unroll
        for (int i = 0; i < 8; i++) {
            float2 d; d.x = av[i]; d.y = av[i];
            *(float2*)&As2[0][aK + i][aRow * 2] = d;
        }
    }
    CP_WAIT0();
    __syncthreads();

    for (int ch = 0; ch < 32; ch++) {
        int buf = ch & 1;
        if (ch < 31) {
            const float* Bp = BpBase + (size_t)(ch + 1) * 16 * NL;
            u32 bDst = (buf ? bDst0 : bDst1);
            CP_ASYNC16(bDst, Bp);
            CP_ASYNC16(bDst + 16, Bp + 4);
            CP_COMMIT();
            const float* Ap = ApBase + (ch + 1) * 16;
            a4lo = *(const float4*)Ap;
            a4hi = *(const float4*)(Ap + 4);
        }
#pragma unroll
        for (int kk = 0; kk < 16; kk++) {
            u64 ar2[8], br2[4];
            // A: 4x LDS.128 over contiguous dup pairs (broadcast within ty-group)
#pragma unroll
            for (int i = 0; i < 4; i++) {
                ulonglong2 a2 = *(const ulonglong2*)&As2[buf][kk][(ty * 8 + 2 * i) * 2];
                ar2[2 * i] = a2.x;
                ar2[2 * i + 1] = a2.y;
            }
            // B: 4x LDS.64 strided (conflict-free mapping)
#pragma unroll
            for (int jp = 0; jp < 4; jp++)
                br2[jp] = *(const u64*)&Bs[buf][kk][jp * 32 + tx * 2];
#pragma unroll
            for (int i = 0; i < 8; i++)
#pragma unroll
                for (int jp = 0; jp < 4; jp++) fma2(acc[i][jp], ar2[i], br2[jp]);
        }
        if (ch < 31) {
            float av[8] = {a4lo.x, a4lo.y, a4lo.z, a4lo.w, a4hi.x, a4hi.y, a4hi.z, a4hi.w};
#pragma unroll
            for (int i = 0; i < 8; i++) {
                float2 d; d.x = av[i]; d.y = av[i];
                *(float2*)&As2[buf ^ 1][aK + i][aRow * 2] = d;
            }
        }
        CP_WAIT0();
        __syncthreads();
    }

#pragma unroll
    for (int i = 0; i < 8; i++) {
        int m = rowBase + ty * 8 + i;
        float bv = bias[m];
#pragma unroll
        for (int jp = 0; jp < 4; jp++) {
            float2 val = *(float2*)&acc[i][jp];
            val.x += bv;
            val.y += bv;
            *(float2*)&C[(size_t)m * NL + colBase + jp * 32 + tx * 2] = val;
        }
    }
}

__global__ __launch_bounds__(256, 1) void k_gemm1(const float* __restrict__ q,
                                                  const float* __restrict__ k,
                                                  const float* __restrict__ v,
                                                  const float* __restrict__ w,
                                                  const float* __restrict__ bias) {
    int z = blockIdx.z, p = z >> 3, b = z & 7;
    const float* src = (p == 0) ? q : (p == 1) ? k : v;
    sgemm_x2(w + (size_t)p * 512 * 512, src + (size_t)b * NC * NL,
             &g_Y[z][0][0], bias + p * 512);
}

__global__ __launch_bounds__(256, 1) void k_gemm3(const float* __restrict__ w,
                                                  const float* __restrict__ bias) {
    int z = blockIdx.z;
    sgemm_x2(w, &g_X[z][0][0], &g_Z[z][0][0], bias);
}

// ---------------- BN stats (fp64 accumulation) ----------------
__device__ __forceinline__ void block_reduce2(double& s1, double& s2) {
    __shared__ double r1[256], r2[256];
    int tid = threadIdx.x;
    r1[tid] = s1; r2[tid] = s2;
    __syncthreads();
    for (int s = 128; s > 0; s >>= 1) {
        if (tid < s) { r1[tid] += r1[tid + s]; r2[tid] += r2[tid + s]; }
        __syncthreads();
    }
    s1 = r1[0]; s2 = r2[0];
}

__global__ __launch_bounds__(256) void k_stats_branch() {
    int p = blockIdx.x >> 9, c = blockIdx.x & 511;
    double s1 = 0.0, s2 = 0.0;
    for (int i = threadIdx.x; i < 8192; i += 256) {
        int b = i >> 10, n = i & 1023;
        float y = g_Y[p * 8 + b][c][n];
        s1 += (double)y;
        s2 += (double)y * (double)y;
    }
    block_reduce2(s1, s2);
    if (threadIdx.x == 0) {
        double m = s1 / 8192.0;
        double var = s2 / 8192.0 - m * m;
        g_bmean[p][c] = (float)m;
        g_binv[p][c] = (float)(1.0 / sqrt(var + 1e-5));
    }
}

__global__ __launch_bounds__(256) void k_stats_final() {
    int c = blockIdx.x;
    double s1 = 0.0, s2 = 0.0;
    for (int i = threadIdx.x; i < 32768; i += 256) {
        int zz = i >> 10, n = i & 1023;
        float y = g_Z[zz][c][n];
        s1 += (double)y;
        s2 += (double)y * (double)y;
    }
    block_reduce2(s1, s2);
    if (threadIdx.x == 0) {
        double m = s1 / 32768.0;
        double var = s2 / 32768.0 - m * m;
        g_fmean[c] = (float)m;
        g_finv[c] = (float)(1.0 / sqrt(var + 1e-5));
    }
}

// ---------------- spike + pack ----------------
__global__ __launch_bounds__(256) void k_spike_q(const float* __restrict__ gamma,
                                                 const float* __restrict__ beta) {
    int rep = blockIdx.x & 3;
    int bh = blockIdx.x >> 2;
    int b = bh >> 3, h = bh & 7;
    __shared__ float sm[64], si[64], sg[64], sb[64];
    if (threadIdx.x < 64) {
        int c = h * 64 + threadIdx.x;
        sm[threadIdx.x] = g_bmean[0][c];
        si[threadIdx.x] = g_binv[0][c];
        sg[threadIdx.x] = gamma[c];
        sb[threadIdx.x] = beta[c];
    }
    __syncthreads();
    int n = rep * 256 + threadIdx.x;
    u64 bits[4] = {0ull, 0ull, 0ull, 0ull};
    for (int dd = 0; dd < 64; dd++) {
        float y = g_Y[b][h * 64 + dd][n];
        float x = y - sm[dd];
        x = sg[dd] * x;
        x = x * si[dd];
        x = x + sb[dd];
        unsigned s = lif4_const(x, 1.0f);
        bits[0] |= (u64)(s & 1u) << dd;
        bits[1] |= (u64)((s >> 1) & 1u) << dd;
        bits[2] |= (u64)((s >> 2) & 1u) << dd;
        bits[3] |= (u64)((s >> 3) & 1u) << dd;
    }
#pragma unroll
    for (int t = 0; t < 4; t++) g_Qd[t][b][h][n] = bits[t];
}

__global__ __launch_bounds__(256) void k_spike_kv(const float* __restrict__ kg,
                                                  const float* __restrict__ kb,
                                                  const float* __restrict__ vg,
                                                  const float* __restrict__ vb) {
    int z = blockIdx.x;                 // 0..511
    int p = z >> 8;
    int quarter = z & 3;
    int bh = (z >> 2) & 63;
    int b = bh >> 3, h = bh & 7;
    const float* gamma = p ? vg : kg;
    const float* beta = p ? vb : kb;
    int pb = p + 1;
    int wi = threadIdx.x >> 5, l = threadIdx.x & 31;
    for (int tsk = wi; tsk < 256; tsk += 8) {
        int dd = tsk >> 2, nw = quarter * 4 + (tsk & 3);
        int c = h * 64 + dd;
        float m = g_bmean[pb][c], iv = g_binv[pb][c], gg = gamma[c], bb = beta[c];
        const float* yrow = &g_Y[pb * 8 + b][c][nw * 64];
        float y0 = yrow[l], y1 = yrow[l + 32];
        float x0 = (y0 - m); x0 = gg * x0; x0 = x0 * iv; x0 = x0 + bb;
        float x1 = (y1 - m); x1 = gg * x1; x1 = x1 * iv; x1 = x1 + bb;
        unsigned s0 = lif4_const(x0, 1.0f);
        unsigned s1 = lif4_const(x1, 1.0f);
#pragma unroll
        for (int t = 0; t < 4; t++) {
            u32 lo = __ballot_sync(0xffffffffu, (s0 >> t) & 1u);
            u32 hi = __ballot_sync(0xffffffffu, (s1 >> t) & 1u);
            if (l == 0) g_KVn[p][t][b][h][dd][nw] = (u64)lo | ((u64)hi << 32);
        }
    }
}

// ---------------- ktv via popcount ----------------
__global__ __launch_bounds__(256) void k_ktv() {
    int z = blockIdx.x;                 // 0..255
    int t = z >> 6;
    int bh = z & 63;
    int b = bh >> 3, h = bh & 7;
    __shared__ u64 Kb[64][16];
    __shared__ u64 Vb[64][16];
    const u64* ks = &g_KVn[0][t][b][h][0][0];
    const u64* vs = &g_KVn[1][t][b][h][0][0];
    for (int i = threadIdx.x; i < 1024; i += 256) {
        ((u64*)Kb)[i] = ks[i];
        ((u64*)Vb)[i] = vs[i];
    }
    __syncthreads();
    int d = threadIdx.x >> 2;
    int e0 = (threadIdx.x & 3) * 16;
    for (int j = 0; j < 16; j++) {
        int e = e0 + j;
        int s = 0;
#pragma unroll
        for (int w = 0; w < 16; w++) s += __popcll(Kb[d][w] & Vb[e][w]);
        g_ktv[t][b][h][d][e] = (float)s;
    }
}

// ---------------- att + attn-LIF -> binary X (exact) ----------------
__global__ __launch_bounds__(128) void k_att() {
    int nt = blockIdx.x, h = blockIdx.y, b = blockIdx.z;
    int n = nt * 128 + threadIdx.x;
    __shared__ float sk[2][64][65];
    u64 qb[4];
#pragma unroll
    for (int t = 0; t < 4; t++) qb[t] = g_Qd[t][b][h][n];
    float v[64];
#pragma unroll
    for (int e = 0; e < 64; e++) v[e] = 0.f;

    for (int t = 0; t < 4; t++) {
        if ((t & 1) == 0) {
            __syncthreads();
            for (int i = threadIdx.x; i < 2 * 4096; i += 128) {
                int tt = i >> 12;
                int r = i & 4095;
                sk[tt][r >> 6][r & 63] = g_ktv[t + tt][b][h][r >> 6][r & 63];
            }
            __syncthreads();
        }
        float a[64];
#pragma unroll
        for (int e = 0; e < 64; e++) a[e] = 0.f;
        u64 m = qb[t];
        while (m) {
            int d = __ffsll((long long)m) - 1;
            m &= m - 1;
            const float* row = &sk[t & 1][d][0];
#pragma unroll
            for (int e = 0; e < 64; e++) a[e] += row[e];
        }
        int zo = t * 8 + b;
#pragma unroll
        for (int e = 0; e < 64; e++) {
            float x = a[e] * 0.125f;                 // exact (dyadic integers)
            v[e] = v[e] + (x - v[e]) * 0.5f;         // exact
            float sp = (v[e] >= 0.5f) ? 1.f : 0.f;
            g_X[zo][h * 64 + e][n] = sp;
            v[e] *= (1.f - sp);
        }
    }
}

// ---------------- final BN + LIF(1.0) ----------------
__global__ __launch_bounds__(256) void k_final(const float* __restrict__ gamma,
                                               const float* __restrict__ beta,
                                               float* __restrict__ out) {
    long idx = (long)blockIdx.x * 256 + threadIdx.x;
    int n = (int)(idx & 1023);
    int c = (int)((idx >> 10) & 511);
    int b = (int)(idx >> 19);
    float m = g_fmean[c], iv = g_finv[c], gg = gamma[c], bb = beta[c];
    float v = 0.f;
#pragma unroll
    for (int t = 0; t < 4; t++) {
        float x = g_Z[t * 8 + b][c][n];
        x = x - m;
        x = gg * x;
        x = x * iv;
        x = x + bb;
        v = __fadd_rn(v, __fmul_rn(__fsub_rn(x, v), 0.5f));
        float s = (v >= 1.0f) ? 1.f : 0.f;
        out[(((long)(t * 8 + b) * NC + c) << 10) + n] = s;
        v *= (1.f - s);
    }
}

extern "C" void kernel_launch(void* const* d_in, const int* in_sizes, int n_in,
                              void* d_out, int out_size) {
    const float* q       = (const float*)d_in[0];
    const float* k       = (const float*)d_in[1];
    const float* v       = (const float*)d_in[2];
    const float* in_w    = (const float*)d_in[3];
    const float* in_b    = (const float*)d_in[4];
    const float* q_gamma = (const float*)d_in[5];
    const float* q_beta  = (const float*)d_in[6];
    const float* k_gamma = (const float*)d_in[7];
    const float* k_beta  = (const float*)d_in[8];
    const float* v_gamma = (const float*)d_in[9];
    const float* v_beta  = (const float*)d_in[10];
    const float* proj_w  = (const float*)d_in[11];
    const float* proj_b  = (const float*)d_in[12];
    const float* p_gamma = (const float*)d_in[13];
    const float* p_beta  = (const float*)d_in[14];
    float* out = (float*)d_out;

    k_nop1<<<1, 32>>>();
    k_nop2<<<1, 32>>>();
    k_nop3<<<1, 32>>>();
    k_gemm1<<<dim3(NL / 128, NC / 128, 24), 256>>>(q, k, v, in_w, in_b);
    k_stats_branch<<<1536, 256>>>();
    k_spike_q<<<256, 256>>>(q_gamma, q_beta);
    k_spike_kv<<<512, 256>>>(k_gamma, k_beta, v_gamma, v_beta);
    k_ktv<<<256, 256>>>();
    k_att<<<dim3(8, 8, 8), 128>>>();
    k_gemm3<<<dim3(NL / 128, NC / 128, 32), 256>>>(proj_w, proj_b);
    k_stats_final<<<512, 256>>>();
    k_final<<<16384, 256>>>(p_gamma, p_beta, out);
}

// round 14
// speedup vs baseline: 2.0211x; 2.0211x over previous
#include <cuda_runtime.h>
#include <cstdint>

// Spikformer SSA on GB300 — fp32 GEMMs via packed fma.rn.f32x2 (R12 config:
// 128x128 tile, 2 CTAs/SM — empirically best; fma% invariant to scheduling).
// Numerics: sequential ascending-k fp32 FMA chain per output == cuBLAS sgemm
// == reference (rel_err 0.0). DO NOT reorder accumulation.
// R14: BN stats fused into GEMM epilogues (fp64 atomics + tiny finalize);
// spike_q/spike_kv merged into one launch.

#define NC 512
#define NL 1024

typedef unsigned long long u64;
typedef unsigned int u32;

// ---------------- device globals ----------------
__device__ float g_Y[24][NC][NL];
__device__ float g_Z[32][NC][NL];
__device__ float g_X[32][NC][NL];
__device__ float g_bmean[3][NC];
__device__ float g_binv[3][NC];
__device__ u64   g_KVn[2][4][8][8][64][16];
__device__ u64   g_Qd[4][8][8][NL];
__device__ float g_ktv[4][8][8][64][64];
__device__ float g_fmean[NC];
__device__ float g_finv[NC];
__device__ double g_bs1[3][NC], g_bs2[3][NC];   // branch stats accumulators
__device__ double g_fs1[NC], g_fs2[NC];          // final stats accumulators
__device__ int   g_sink;

// ---------------- helpers ----------------
__device__ __forceinline__ unsigned lif4_const(float x, float vth) {
    float v = 0.f;
    unsigned bits = 0;
#pragma unroll
    for (int t = 0; t < 4; t++) {
        v = __fadd_rn(v, __fmul_rn(__fsub_rn(x, v), 0.5f));
        if (v >= vth) { bits |= 1u << t; v = 0.f; }
    }
    return bits;
}

__device__ __forceinline__ void fma2(u64& c, u64 a, u64 b) {
    asm("fma.rn.f32x2 %0, %1, %2, %3;" : "=l"(c) : "l"(a), "l"(b), "l"(c));
}

__device__ __forceinline__ u32 smem_u32(const void* p) {
    u32 a;
    asm("{ .reg .u64 t; cvta.to.shared.u64 t, %1; cvt.u32.u64 %0, t; }" : "=r"(a) : "l"(p));
    return a;
}

#define CP_ASYNC16(dst, src) \
    asm volatile("cp.async.ca.shared.global [%0], [%1], 16;" :: "r"(dst), "l"(src))
#define CP_COMMIT() asm volatile("cp.async.commit_group;" ::: "memory")
#define CP_WAIT0()  asm volatile("cp.async.wait_group 0;" ::: "memory")

// dummy kernels so ncu's fixed "-s 5 -c 1" capture lands on k_gemm1
__global__ void k_nop1() { if (threadIdx.x == 1u << 31) g_sink = 1; }
__global__ void k_nop2() { if (threadIdx.x == 1u << 31) g_sink = 2; }

// zero the stats accumulators each replay (graph-persistent globals)
__global__ void k_zero_stats() {
    int i = blockIdx.x * 256 + threadIdx.x;       // 4096 >= 3*512*2 + 512*2
    if (i < 1536) { g_bs1[0][i] = 0.0; g_bs2[0][i] = 0.0; }
    else if (i < 2048) { g_fs1[i - 1536] = 0.0; g_fs2[i - 1536] = 0.0; }
}

// ---------------- packed-fp32 SGEMM: C_tile[128,128], K=512, chunk=16, dbuf ------
// Thread (tx,ty): rows ty*8..+8, col pairs jp*32+tx*2. Fused per-channel stats.
__device__ __forceinline__ void sgemm_x2(const float* __restrict__ A,
                                         const float* __restrict__ B,
                                         float* __restrict__ C,
                                         const float* __restrict__ bias,
                                         double* __restrict__ s1acc,
                                         double* __restrict__ s2acc,
                                         int chanBase) {
    __shared__ float As2[2][16][256];   // A duplicated (v,v): 16KB per buffer
    __shared__ float Bs[2][16][128];    // B verbatim: 8KB per buffer
    const int tid = threadIdx.x;
    const int tx = tid & 15, ty = tid >> 4;
    const int rowBase = blockIdx.y * 128, colBase = blockIdx.x * 128;

    const int aRow = tid >> 1, aK = (tid & 1) * 8;
    const float* ApBase = A + (size_t)(rowBase + aRow) * 512 + aK;
    const int bRow = tid >> 4, bSeg = tid & 15;
    const float* BpBase = B + (size_t)bRow * NL + colBase + bSeg * 8;
    u32 bDst0 = smem_u32(&Bs[0][bRow][bSeg * 8]);
    u32 bDst1 = smem_u32(&Bs[1][bRow][bSeg * 8]);

    u64 acc[8][4];
#pragma unroll
    for (int i = 0; i < 8; i++)
#pragma unroll
        for (int j = 0; j < 4; j++) acc[i][j] = 0ull;

    float4 a4lo, a4hi;

    CP_ASYNC16(bDst0, BpBase);
    CP_ASYNC16(bDst0 + 16, BpBase + 4);
    CP_COMMIT();
    a4lo = *(const float4*)ApBase;
    a4hi = *(const float4*)(ApBase + 4);
    {
        float av[8] = {a4lo.x, a4lo.y, a4lo.z, a4lo.w, a4hi.x, a4hi.y, a4hi.z, a4hi.w};
#pragma unroll
        for (int i = 0; i < 8; i++) {
            float2 d; d.x = av[i]; d.y = av[i];
            *(float2*)&As2[0][aK + i][aRow * 2] = d;
        }
    }
    CP_WAIT0();
    __syncthreads();

    for (int ch = 0; ch < 32; ch++) {
        int buf = ch & 1;
        if (ch < 31) {
            const float* Bp = BpBase + (size_t)(ch + 1) * 16 * NL;
            u32 bDst = (buf ? bDst0 : bDst1);
            CP_ASYNC16(bDst, Bp);
            CP_ASYNC16(bDst + 16, Bp + 4);
            CP_COMMIT();
            const float* Ap = ApBase + (ch + 1) * 16;
            a4lo = *(const float4*)Ap;
            a4hi = *(const float4*)(Ap + 4);
        }
#pragma unroll
        for (int kk = 0; kk < 16; kk++) {
            u64 ar2[8], br2[4];
#pragma unroll
            for (int i = 0; i < 4; i++) {
                ulonglong2 a2 = *(const ulonglong2*)&As2[buf][kk][(ty * 8 + 2 * i) * 2];
                ar2[2 * i] = a2.x;
                ar2[2 * i + 1] = a2.y;
            }
#pragma unroll
            for (int jp = 0; jp < 4; jp++)
                br2[jp] = *(const u64*)&Bs[buf][kk][jp * 32 + tx * 2];
#pragma unroll
            for (int i = 0; i < 8; i++)
#pragma unroll
                for (int jp = 0; jp < 4; jp++) fma2(acc[i][jp], ar2[i], br2[jp]);
        }
        if (ch < 31) {
            float av[8] = {a4lo.x, a4lo.y, a4lo.z, a4lo.w, a4hi.x, a4hi.y, a4hi.z, a4hi.w};
#pragma unroll
            for (int i = 0; i < 8; i++) {
                float2 d; d.x = av[i]; d.y = av[i];
                *(float2*)&As2[buf ^ 1][aK + i][aRow * 2] = d;
            }
        }
        CP_WAIT0();
        __syncthreads();
    }

#pragma unroll
    for (int i = 0; i < 8; i++) {
        int m = rowBase + ty * 8 + i;
        float bv = bias[m];
        double s1 = 0.0, s2 = 0.0;
#pragma unroll
        for (int jp = 0; jp < 4; jp++) {
            float2 val = *(float2*)&acc[i][jp];
            val.x += bv;
            val.y += bv;
            *(float2*)&C[(size_t)m * NL + colBase + jp * 32 + tx * 2] = val;
            s1 += (double)val.x + (double)val.y;
            s2 += (double)val.x * (double)val.x + (double)val.y * (double)val.y;
        }
        // half-warp (16 tx lanes) reduction, then one atomic per row
#pragma unroll
        for (int off = 8; off > 0; off >>= 1) {
            s1 += __shfl_down_sync(0xffffffffu, s1, off, 16);
            s2 += __shfl_down_sync(0xffffffffu, s2, off, 16);
        }
        if (tx == 0) {
            atomicAdd(&s1acc[chanBase + m], s1);
            atomicAdd(&s2acc[chanBase + m], s2);
        }
    }
}

__global__ __launch_bounds__(256, 2) void k_gemm1(const float* __restrict__ q,
                                                  const float* __restrict__ k,
                                                  const float* __restrict__ v,
                                                  const float* __restrict__ w,
                                                  const float* __restrict__ bias) {
    int z = blockIdx.z, p = z >> 3, b = z & 7;
    const float* src = (p == 0) ? q : (p == 1) ? k : v;
    sgemm_x2(w + (size_t)p * 512 * 512, src + (size_t)b * NC * NL,
             &g_Y[z][0][0], bias + p * 512, &g_bs1[0][0], &g_bs2[0][0], p * 512);
}

__global__ __launch_bounds__(256, 2) void k_gemm3(const float* __restrict__ w,
                                                  const float* __restrict__ bias) {
    int z = blockIdx.z;
    sgemm_x2(w, &g_X[z][0][0], &g_Z[z][0][0], bias, &g_fs1[0], &g_fs2[0], 0);
}

// ---------------- stats finalize (tiny) ----------------
__global__ void k_fin_branch() {
    int i = blockIdx.x * 256 + threadIdx.x;     // 1536
    if (i >= 1536) return;
    double m = g_bs1[0][i] / 8192.0;
    double var = g_bs2[0][i] / 8192.0 - m * m;
    g_bmean[0][i] = (float)m;
    g_binv[0][i] = (float)(1.0 / sqrt(var + 1e-5));
}

__global__ void k_fin_final() {
    int i = blockIdx.x * 256 + threadIdx.x;     // 512
    if (i >= 512) return;
    double m = g_fs1[i] / 32768.0;
    double var = g_fs2[i] / 32768.0 - m * m;
    g_fmean[i] = (float)m;
    g_finv[i] = (float)(1.0 / sqrt(var + 1e-5));
}

// ---------------- merged spike + pack (q: blocks 0..255, kv: 256..767) ----------
__global__ __launch_bounds__(256) void k_spike(const float* __restrict__ qg,
                                               const float* __restrict__ qb_,
                                               const float* __restrict__ kg,
                                               const float* __restrict__ kb,
                                               const float* __restrict__ vg,
                                               const float* __restrict__ vb) {
    if (blockIdx.x < 256) {
        // ---- q path ----
        int rep = blockIdx.x & 3;
        int bh = blockIdx.x >> 2;
        int b = bh >> 3, h = bh & 7;
        __shared__ float sm[64], si[64], sg[64], sb[64];
        if (threadIdx.x < 64) {
            int c = h * 64 + threadIdx.x;
            sm[threadIdx.x] = g_bmean[0][c];
            si[threadIdx.x] = g_binv[0][c];
            sg[threadIdx.x] = qg[c];
            sb[threadIdx.x] = qb_[c];
        }
        __syncthreads();
        int n = rep * 256 + threadIdx.x;
        u64 bits[4] = {0ull, 0ull, 0ull, 0ull};
        for (int dd = 0; dd < 64; dd++) {
            float y = g_Y[b][h * 64 + dd][n];
            float x = y - sm[dd];
            x = sg[dd] * x;
            x = x * si[dd];
            x = x + sb[dd];
            unsigned s = lif4_const(x, 1.0f);
            bits[0] |= (u64)(s & 1u) << dd;
            bits[1] |= (u64)((s >> 1) & 1u) << dd;
            bits[2] |= (u64)((s >> 2) & 1u) << dd;
            bits[3] |= (u64)((s >> 3) & 1u) << dd;
        }
#pragma unroll
        for (int t = 0; t < 4; t++) g_Qd[t][b][h][n] = bits[t];
    } else {
        // ---- kv path ----
        int z = blockIdx.x - 256;       // 0..511
        int p = z >> 8;
        int quarter = z & 3;
        int bh = (z >> 2) & 63;
        int b = bh >> 3, h = bh & 7;
        const float* gamma = p ? vg : kg;
        const float* beta = p ? vb : kb;
        int pb = p + 1;
        int wi = threadIdx.x >> 5, l = threadIdx.x & 31;
        for (int tsk = wi; tsk < 256; tsk += 8) {
            int dd = tsk >> 2, nw = quarter * 4 + (tsk & 3);
            int c = h * 64 + dd;
            float m = g_bmean[pb][c], iv = g_binv[pb][c], gg = gamma[c], bb = beta[c];
            const float* yrow = &g_Y[pb * 8 + b][c][nw * 64];
            float y0 = yrow[l], y1 = yrow[l + 32];
            float x0 = (y0 - m); x0 = gg * x0; x0 = x0 * iv; x0 = x0 + bb;
            float x1 = (y1 - m); x1 = gg * x1; x1 = x1 * iv; x1 = x1 + bb;
            unsigned s0 = lif4_const(x0, 1.0f);
            unsigned s1 = lif4_const(x1, 1.0f);
#pragma unroll
            for (int t = 0; t < 4; t++) {
                u32 lo = __ballot_sync(0xffffffffu, (s0 >> t) & 1u);
                u32 hi = __ballot_sync(0xffffffffu, (s1 >> t) & 1u);
                if (l == 0) g_KVn[p][t][b][h][dd][nw] = (u64)lo | ((u64)hi << 32);
            }
        }
    }
}

// ---------------- ktv via popcount ----------------
__global__ __launch_bounds__(256) void k_ktv() {
    int z = blockIdx.x;                 // 0..255
    int t = z >> 6;
    int bh = z & 63;
    int b = bh >> 3, h = bh & 7;
    __shared__ u64 Kb[64][16];
    __shared__ u64 Vb[64][16];
    const u64* ks = &g_KVn[0][t][b][h][0][0];
    const u64* vs = &g_KVn[1][t][b][h][0][0];
    for (int i = threadIdx.x; i < 1024; i += 256) {
        ((u64*)Kb)[i] = ks[i];
        ((u64*)Vb)[i] = vs[i];
    }
    __syncthreads();
    int d = threadIdx.x >> 2;
    int e0 = (threadIdx.x & 3) * 16;
    for (int j = 0; j < 16; j++) {
        int e = e0 + j;
        int s = 0;
#pragma unroll
        for (int w = 0; w < 16; w++) s += __popcll(Kb[d][w] & Vb[e][w]);
        g_ktv[t][b][h][d][e] = (float)s;
    }
}

// ---------------- att + attn-LIF -> binary X (exact) ----------------
__global__ __launch_bounds__(128) void k_att() {
    int nt = blockIdx.x, h = blockIdx.y, b = blockIdx.z;
    int n = nt * 128 + threadIdx.x;
    __shared__ float sk[2][64][65];
    u64 qb[4];
#pragma unroll
    for (int t = 0; t < 4; t++) qb[t] = g_Qd[t][b][h][n];
    float v[64];
#pragma unroll
    for (int e = 0; e < 64; e++) v[e] = 0.f;

    for (int t = 0; t < 4; t++) {
        if ((t & 1) == 0) {
            __syncthreads();
            for (int i = threadIdx.x; i < 2 * 4096; i += 128) {
                int tt = i >> 12;
                int r = i & 4095;
                sk[tt][r >> 6][r & 63] = g_ktv[t + tt][b][h][r >> 6][r & 63];
            }
            __syncthreads();
        }
        float a[64];
#pragma unroll
        for (int e = 0; e < 64; e++) a[e] = 0.f;
        u64 m = qb[t];
        while (m) {
            int d = __ffsll((long long)m) - 1;
            m &= m - 1;
            const float* row = &sk[t & 1][d][0];
#pragma unroll
            for (int e = 0; e < 64; e++) a[e] += row[e];
        }
        int zo = t * 8 + b;
#pragma unroll
        for (int e = 0; e < 64; e++) {
            float x = a[e] * 0.125f;                 // exact (dyadic integers)
            v[e] = v[e] + (x - v[e]) * 0.5f;         // exact
            float sp = (v[e] >= 0.5f) ? 1.f : 0.f;
            g_X[zo][h * 64 + e][n] = sp;
            v[e] *= (1.f - sp);
        }
    }
}

// ---------------- final BN + LIF(1.0) ----------------
__global__ __launch_bounds__(256) void k_final(const float* __restrict__ gamma,
                                               const float* __restrict__ beta,
                                               float* __restrict__ out) {
    long idx = (long)blockIdx.x * 256 + threadIdx.x;
    int n = (int)(idx & 1023);
    int c = (int)((idx >> 10) & 511);
    int b = (int)(idx >> 19);
    float m = g_fmean[c], iv = g_finv[c], gg = gamma[c], bb = beta[c];
    float v = 0.f;
#pragma unroll
    for (int t = 0; t < 4; t++) {
        float x = g_Z[t * 8 + b][c][n];
        x = x - m;
        x = gg * x;
        x = x * iv;
        x = x + bb;
        v = __fadd_rn(v, __fmul_rn(__fsub_rn(x, v), 0.5f));
        float s = (v >= 1.0f) ? 1.f : 0.f;
        out[(((long)(t * 8 + b) * NC + c) << 10) + n] = s;
        v *= (1.f - s);
    }
}

extern "C" void kernel_launch(void* const* d_in, const int* in_sizes, int n_in,
                              void* d_out, int out_size) {
    const float* q       = (const float*)d_in[0];
    const float* k       = (const float*)d_in[1];
    const float* v       = (const float*)d_in[2];
    const float* in_w    = (const float*)d_in[3];
    const float* in_b    = (const float*)d_in[4];
    const float* q_gamma = (const float*)d_in[5];
    const float* q_beta  = (const float*)d_in[6];
    const float* k_gamma = (const float*)d_in[7];
    const float* k_beta  = (const float*)d_in[8];
    const float* v_gamma = (const float*)d_in[9];
    const float* v_beta  = (const float*)d_in[10];
    const float* proj_w  = (const float*)d_in[11];
    const float* proj_b  = (const float*)d_in[12];
    const float* p_gamma = (const float*)d_in[13];
    const float* p_beta  = (const float*)d_in[14];
    float* out = (float*)d_out;

    k_nop1<<<1, 32>>>();
    k_nop2<<<1, 32>>>();
    k_zero_stats<<<16, 256>>>();
    k_gemm1<<<dim3(NL / 128, NC / 128, 24), 256>>>(q, k, v, in_w, in_b);
    k_fin_branch<<<6, 256>>>();
    k_spike<<<768, 256>>>(q_gamma, q_beta, k_gamma, k_beta, v_gamma, v_beta);
    k_ktv<<<256, 256>>>();
    k_att<<<dim3(8, 8, 8), 128>>>();
    k_gemm3<<<dim3(NL / 128, NC / 128, 32), 256>>>(proj_w, proj_b);
    k_fin_final<<<2, 256>>>();
    k_final<<<16384, 256>>>(p_gamma, p_beta, out);
}